// round 10
// baseline (speedup 1.0000x reference)
#include <cuda_runtime.h>
#include <cuda_bf16.h>
#include <cstdint>
#include <math.h>

#define NH     16
#define NSEQ   8192
#define EDIM   64
#define CHUNKN 512
#define NCH    16
#define WCOLS  15872
#define MTILE  128
#define SCALE  0.125f

// ---- bf16 hi/lo scratch planes: [0]=Khi [1]=Klo [2]=Vhi [3]=Vlo ----
#define SCR_ELEMS (16u * 8192u * 64u)   // 8388608
__device__ __nv_bfloat16 g_scr[4][SCR_ELEMS];

// ---- SMEM byte offsets; all K/V/Q rows stride 144B (64 bf16 + 8 pad) ----
#define SM_QHI   0
#define SM_QLO   18432
#define SM_K0    36864          // hi at +0, lo at +18432
#define SM_K1    73728
#define SM_V0    110592
#define SM_V1    147456
#define SM_SUMS  184320         // 16 warps x 16 rows fp32
#define SM_INV   185344         // 128 fp32
#define SM_TOTAL 185856
#define SM_OBUF  SM_QHI         // alias after Q frags preloaded: 128 x 66 fp32

__device__ __forceinline__ uint32_t s2u(const void* p) {
    uint32_t a;
    asm("{ .reg .u64 t; cvta.to.shared.u64 t, %1; cvt.u32.u64 %0, t; }" : "=r"(a) : "l"(p));
    return a;
}
__device__ __forceinline__ void ldmx4(uint32_t addr, uint32_t* r) {
    asm volatile("ldmatrix.sync.aligned.m8n8.x4.shared.b16 {%0,%1,%2,%3}, [%4];"
                 : "=r"(r[0]), "=r"(r[1]), "=r"(r[2]), "=r"(r[3]) : "r"(addr));
}
__device__ __forceinline__ void ldmx2(uint32_t addr, uint32_t* r) {
    asm volatile("ldmatrix.sync.aligned.m8n8.x2.shared.b16 {%0,%1}, [%2];"
                 : "=r"(r[0]), "=r"(r[1]) : "r"(addr));
}
__device__ __forceinline__ void ldmx2t(uint32_t addr, uint32_t* r) {
    asm volatile("ldmatrix.sync.aligned.m8n8.x2.trans.shared.b16 {%0,%1}, [%2];"
                 : "=r"(r[0]), "=r"(r[1]) : "r"(addr));
}
__device__ __forceinline__ void mma16816(float* d, const uint32_t* a, const uint32_t* b) {
    asm volatile("mma.sync.aligned.m16n8k16.row.col.f32.bf16.bf16.f32 "
                 "{%0,%1,%2,%3},{%4,%5,%6,%7},{%8,%9},{%0,%1,%2,%3};"
                 : "+f"(d[0]), "+f"(d[1]), "+f"(d[2]), "+f"(d[3])
                 : "r"(a[0]), "r"(a[1]), "r"(a[2]), "r"(a[3]), "r"(b[0]), "r"(b[1]));
}
__device__ __forceinline__ uint32_t packbf(float lo, float hi) {
    uint32_t r;
    asm("cvt.rn.bf16x2.f32 %0, %1, %2;" : "=r"(r) : "f"(hi), "f"(lo));
    return r;
}
__device__ __forceinline__ float bfval(float x) {
    return __bfloat162float(__float2bfloat16(x));
}
__device__ __forceinline__ void cpa16(uint32_t dst, const void* src) {
    asm volatile("cp.async.cg.shared.global [%0], [%1], 16;" :: "r"(dst), "l"(src));
}
#define CP_COMMIT() asm volatile("cp.async.commit_group;" ::: "memory")
#define CP_WAIT(n)  asm volatile("cp.async.wait_group %0;" :: "n"(n) : "memory")

// =================== pre-kernel: fp32 -> bf16 hi/lo planes ===================
__global__ __launch_bounds__(512)
void convert_kv(const float* __restrict__ key, const float* __restrict__ value)
{
    uint32_t i = blockIdx.x * 512u + threadIdx.x;      // float4 index, exact grid
    float4 kv = ((const float4*)key)[i];
    float4 vv = ((const float4*)value)[i];
    uint2 khi, klo, vhi, vlo;
    khi.x = packbf(kv.x, kv.y); khi.y = packbf(kv.z, kv.w);
    klo.x = packbf(kv.x - bfval(kv.x), kv.y - bfval(kv.y));
    klo.y = packbf(kv.z - bfval(kv.z), kv.w - bfval(kv.w));
    vhi.x = packbf(vv.x, vv.y); vhi.y = packbf(vv.z, vv.w);
    vlo.x = packbf(vv.x - bfval(vv.x), vv.y - bfval(vv.y));
    vlo.y = packbf(vv.z - bfval(vv.z), vv.w - bfval(vv.w));
    ((uint2*)g_scr[0])[i] = khi;
    ((uint2*)g_scr[1])[i] = klo;
    ((uint2*)g_scr[2])[i] = vhi;
    ((uint2*)g_scr[3])[i] = vlo;
}

// =================== main kernel ===================
__global__ __launch_bounds__(512, 1)
void chunked_attn_mma(const float* __restrict__ query, float* __restrict__ out,
                      float* __restrict__ wts)
{
    extern __shared__ char smem[];
    const uint32_t sb = s2u(smem);
    const int tid = threadIdx.x, lane = tid & 31, w = tid >> 5;
    const int strip = w & 7;          // 16-row strip
    const int kh    = w >> 3;         // 64-col half of the 128-key slab

    const int rt = 3 - blockIdx.x;    // long CTAs first
    const int n  = blockIdx.y, h = blockIdx.z;
    const int r0 = rt * MTILE;
    const int m  = (n == 0) ? 0 : n - 1;
    const int nslab = rt + 1;
    const int jend  = nslab * 128;
    const int wcb   = (n == 0) ? 0 : 512 + (n - 1) * 1024;

    const float* qbase = query + ((size_t)h * NSEQ + (size_t)n * CHUNKN + r0) * EDIM;
    const uint32_t gjbase = (uint32_t)h * NSEQ + (uint32_t)m * CHUNKN;   // key-row base

    const uint32_t kbuf[2] = {sb + SM_K0, sb + SM_K1};
    const uint32_t vbuf[2] = {sb + SM_V0, sb + SM_V1};

    // ---- prefetch slab 0 (cp.async) ----
    {
        for (int i = tid; i < 4096; i += 512) {
            int arr = i >> 10, row = (i >> 3) & 127, seg = i & 7;
            uint32_t base = (arr < 2) ? kbuf[0] : vbuf[0];
            uint32_t dst = base + ((arr & 1) ? 18432u : 0u) + (uint32_t)row * 144 + seg * 16;
            const __nv_bfloat16* src = g_scr[arr] + ((size_t)(gjbase + row) << 6) + seg * 8;
            cpa16(dst, src);
        }
        CP_COMMIT();
    }

    // ---- zero-fill dead weight columns ----
    {
        const float4 z4 = make_float4(0.f, 0.f, 0.f, 0.f);
        for (int r = w; r < MTILE; r += 16) {
            float* wr = wts + ((size_t)h * CHUNKN + r0 + r) * WCOLS + wcb;
            for (int c = jend + lane * 4; c < 512; c += 128) *(float4*)(wr + c) = z4;
            if (n > 0)
                for (int c = 512 + lane * 4; c < 1024; c += 128) *(float4*)(wr + c) = z4;
        }
    }

    // ---- Q fill: bf16 hi/lo, pre-scaled ----
    for (int idx = tid; idx < MTILE * 16; idx += 512) {
        int row = idx >> 4, c4 = (idx & 15) << 2;
        float4 qv = *(const float4*)(qbase + (size_t)row * EDIM + c4);
        float f[4] = {qv.x * SCALE, qv.y * SCALE, qv.z * SCALE, qv.w * SCALE};
        uint2 hv, lv;
        hv.x = packbf(f[0], f[1]); hv.y = packbf(f[2], f[3]);
        lv.x = packbf(f[0] - bfval(f[0]), f[1] - bfval(f[1]));
        lv.y = packbf(f[2] - bfval(f[2]), f[3] - bfval(f[3]));
        uint32_t o = (uint32_t)row * 144 + (uint32_t)c4 * 2;
        *(uint2*)(smem + SM_QHI + o) = hv;
        *(uint2*)(smem + SM_QLO + o) = lv;
    }
    __syncthreads();   // Q visible

    // ---- preload Q fragments (fixed for all slabs) ----
    uint32_t qh[4][4], ql[4][4];
    {
        const uint32_t aQ = sb + (uint32_t)((strip * 16 + (lane & 15)) * 144 + (lane >> 4) * 16);
        #pragma unroll
        for (int kc = 0; kc < 4; kc++) {
            ldmx4(aQ + SM_QHI + kc * 32, qh[kc]);
            ldmx4(aQ + SM_QLO + kc * 32, ql[kc]);
        }
    }

    float oacc[8][4];
    #pragma unroll
    for (int t = 0; t < 8; t++)
        #pragma unroll
        for (int u = 0; u < 4; u++) oacc[t][u] = 0.f;
    float rs0 = 0.f, rs1 = 0.f;

    const int rlo = r0 + strip * 16 + (lane >> 2);
    const int rhi = rlo + 8;
    const uint32_t bKoff = (uint32_t)((kh * 64 + (lane & 7)) * 144 + ((lane >> 3) & 1) * 16);
    const uint32_t bVoff = (uint32_t)((kh * 64 + (lane & 15)) * 144);

    for (int kt = 0; kt < nslab; kt++) {
        const int p = kt & 1;
        if (kt + 1 < nslab) {   // prefetch next slab into the other buffer
            for (int i = tid; i < 4096; i += 512) {
                int arr = i >> 10, row = (i >> 3) & 127, seg = i & 7;
                uint32_t base = (arr < 2) ? kbuf[1 - p] : vbuf[1 - p];
                uint32_t dst = base + ((arr & 1) ? 18432u : 0u) + (uint32_t)row * 144 + seg * 16;
                const __nv_bfloat16* src =
                    g_scr[arr] + ((size_t)(gjbase + (kt + 1) * 128 + row) << 6) + seg * 8;
                cpa16(dst, src);
            }
            CP_COMMIT();
            CP_WAIT(1);
        } else {
            CP_WAIT(0);
        }
        __syncthreads();        // slab p complete for all warps

        const bool dead = (kt == rt) && (strip * 16 + 15 < kh * 64);
        const uint32_t bK = kbuf[p] + bKoff;
        const uint32_t bV = vbuf[p] + bVoff;

        float sacc[8][4];
        #pragma unroll
        for (int t = 0; t < 8; t++)
            #pragma unroll
            for (int u = 0; u < 4; u++) sacc[t][u] = 0.f;

        if (!dead) {
            // ---- GEMM1: groups of 4 independent accumulators (RAW distance 4) ----
            #pragma unroll
            for (int kc = 0; kc < 4; kc++) {
                #pragma unroll
                for (int tg = 0; tg < 8; tg += 4) {
                    uint32_t bh[4][2], bl[4][2];
                    #pragma unroll
                    for (int j = 0; j < 4; j++) {
                        uint32_t ba = bK + (uint32_t)(tg + j) * 1152 + kc * 32;
                        ldmx2(ba, bh[j]);
                        ldmx2(ba + 18432, bl[j]);
                    }
                    #pragma unroll
                    for (int j = 0; j < 4; j++) mma16816(sacc[tg + j], qh[kc], bh[j]);
                    #pragma unroll
                    for (int j = 0; j < 4; j++) mma16816(sacc[tg + j], qh[kc], bl[j]);
                    #pragma unroll
                    for (int j = 0; j < 4; j++) mma16816(sacc[tg + j], ql[kc], bh[j]);
                }
            }
        }

        // ---- exp + mask + weights STG + pack P ----
        uint32_t phi[8][2], plo[8][2];
        {
            float* wlo = wts + ((size_t)h * CHUNKN + rlo) * WCOLS + wcb
                       + kt * 128 + kh * 64 + 2 * (lane & 3);
            float* whi = wlo + (size_t)8 * WCOLS;
            const int cbase = kt * 128 + kh * 64 + 2 * (lane & 3);
            #pragma unroll
            for (int t = 0; t < 8; t++) {
                int c = cbase + t * 8;
                float p00 = (c     <= rlo) ? __expf(sacc[t][0]) : 0.f;
                float p01 = (c + 1 <= rlo) ? __expf(sacc[t][1]) : 0.f;
                float p10 = (c     <= rhi) ? __expf(sacc[t][2]) : 0.f;
                float p11 = (c + 1 <= rhi) ? __expf(sacc[t][3]) : 0.f;
                rs0 += p00 + p01;  rs1 += p10 + p11;
                *(float2*)(wlo + t * 8) = make_float2(p00, p01);
                *(float2*)(whi + t * 8) = make_float2(p10, p11);
                phi[t][0] = packbf(p00, p01);
                phi[t][1] = packbf(p10, p11);
                plo[t][0] = packbf(p00 - bfval(p00), p01 - bfval(p01));
                plo[t][1] = packbf(p10 - bfval(p10), p11 - bfval(p11));
            }
        }

        if (!dead) {
            // ---- GEMM2: O += P . V, groups of 4 independent accumulators ----
            #pragma unroll
            for (int kc = 0; kc < 4; kc++) {
                uint32_t ah[4] = {phi[2*kc][0], phi[2*kc][1], phi[2*kc+1][0], phi[2*kc+1][1]};
                uint32_t al[4] = {plo[2*kc][0], plo[2*kc][1], plo[2*kc+1][0], plo[2*kc+1][1]};
                #pragma unroll
                for (int tg = 0; tg < 8; tg += 4) {
                    uint32_t bh[4][2], bl[4][2];
                    #pragma unroll
                    for (int j = 0; j < 4; j++) {
                        uint32_t ba = bV + (uint32_t)kc * 2304 + (tg + j) * 16;
                        ldmx2t(ba, bh[j]);
                        ldmx2t(ba + 18432, bl[j]);
                    }
                    #pragma unroll
                    for (int j = 0; j < 4; j++) mma16816(oacc[tg + j], ah, bh[j]);
                    #pragma unroll
                    for (int j = 0; j < 4; j++) mma16816(oacc[tg + j], ah, bl[j]);
                    #pragma unroll
                    for (int j = 0; j < 4; j++) mma16816(oacc[tg + j], al, bh[j]);
                }
            }
        }
        __syncthreads();   // all reads of buf p done before it is refilled
    }

    // ---- rowsum quad-reduce ----
    rs0 += __shfl_xor_sync(0xffffffffu, rs0, 1);
    rs0 += __shfl_xor_sync(0xffffffffu, rs0, 2);
    rs1 += __shfl_xor_sync(0xffffffffu, rs1, 1);
    rs1 += __shfl_xor_sync(0xffffffffu, rs1, 2);
    if ((lane & 3) == 0) {
        float* su = (float*)(smem + SM_SUMS);
        su[w * 16 + (lane >> 2)]     = rs0;
        su[w * 16 + (lane >> 2) + 8] = rs1;
    }
    if (kh == 0) {   // park O partials (stride 66 floats)
        float* ob = (float*)(smem + SM_OBUF);
        int row0 = strip * 16 + (lane >> 2);
        #pragma unroll
        for (int t2 = 0; t2 < 8; t2++) {
            int c = t2 * 8 + 2 * (lane & 3);
            *(float2*)(ob + row0 * 66 + c)       = make_float2(oacc[t2][0], oacc[t2][1]);
            *(float2*)(ob + (row0 + 8) * 66 + c) = make_float2(oacc[t2][2], oacc[t2][3]);
        }
    }
    __syncthreads();

    if (tid < 128) {
        const float* su = (const float*)(smem + SM_SUMS);
        int s = tid >> 4, i = tid & 15;
        ((float*)(smem + SM_INV))[tid] = 1.f / (su[s * 16 + i] + su[(s + 8) * 16 + i]);
    }
    __syncthreads();
    const float* invp = (const float*)(smem + SM_INV);

    if (kh == 1) {
        const float* ob = (const float*)(smem + SM_OBUF);
        int row0 = strip * 16 + (lane >> 2);
        float iv0 = invp[row0], iv1 = invp[row0 + 8];
        float* op = out + ((size_t)h * NSEQ + (size_t)n * CHUNKN + r0 + row0) * EDIM;
        #pragma unroll
        for (int t2 = 0; t2 < 8; t2++) {
            int c = t2 * 8 + 2 * (lane & 3);
            float2 p0 = *(const float2*)(ob + row0 * 66 + c);
            float2 p1 = *(const float2*)(ob + (row0 + 8) * 66 + c);
            *(float2*)(op + c) =
                make_float2((oacc[t2][0] + p0.x) * iv0, (oacc[t2][1] + p0.y) * iv0);
            *(float2*)(op + (size_t)8 * EDIM + c) =
                make_float2((oacc[t2][2] + p1.x) * iv1, (oacc[t2][3] + p1.y) * iv1);
        }
    }

    // ---- rescale weights in-place (live region, L2-warm) ----
    for (int r = w; r < MTILE; r += 16) {
        float iv = invp[r];
        float* wr = wts + ((size_t)h * CHUNKN + r0 + r) * WCOLS + wcb;
        for (int c = lane * 4; c < jend; c += 128) {
            float4 t = *(float4*)(wr + c);
            t.x *= iv; t.y *= iv; t.z *= iv; t.w *= iv;
            *(float4*)(wr + c) = t;
        }
    }
}

extern "C" void kernel_launch(void* const* d_in, const int* in_sizes, int n_in,
                              void* d_out, int out_size)
{
    const float* q = (const float*)d_in[0];
    const float* k = (const float*)d_in[1];
    const float* v = (const float*)d_in[2];
    float* out = (float*)d_out;
    float* wts = out + (size_t)NH * NSEQ * EDIM;

    convert_kv<<<SCR_ELEMS / 4 / 512, 512>>>(k, v);   // 4096 blocks

    cudaFuncSetAttribute(chunked_attn_mma,
                         cudaFuncAttributeMaxDynamicSharedMemorySize, SM_TOTAL);
    dim3 grid(CHUNKN / MTILE, NCH, NH);   // 4 x 16 x 16 = 1024 CTAs
    chunked_attn_mma<<<grid, 512, SM_TOTAL>>>(q, out, wts);
}